// round 5
// baseline (speedup 1.0000x reference)
#include <cuda_runtime.h>
#include <cuda_bf16.h>
#include <cuda_fp16.h>
#include <cstdint>

#define BB 256
#define TT 256
#define EMB 384
#define HH 6
#define DD 64
#define BT (BB*TT)

// ---------------------------------------------------------------------------
// Scratch (__device__ globals — allocation-free rule)
// ---------------------------------------------------------------------------
__device__ __align__(16) __nv_bfloat16 g_qhi[BB * HH * TT * DD];
__device__ __align__(16) __nv_bfloat16 g_qlo[BB * HH * TT * DD];
__device__ __align__(16) __nv_bfloat16 g_khi[BB * HH * TT * DD];
__device__ __align__(16) __nv_bfloat16 g_klo[BB * HH * TT * DD];
__device__ __align__(16) __nv_bfloat16 g_vhi[BB * HH * TT * DD];
__device__ __align__(16) __nv_bfloat16 g_vlo[BB * HH * TT * DD];
__device__ __align__(16) __half        g_xhi[BT * EMB];            // fp16 split of x
__device__ __align__(16) __half        g_xlo[BT * EMB];
__device__ __align__(16) __half        g_wthi[3 * HH * DD * EMB];  // fp16 hi, [n=z*384+h*64+d][e]
__device__ __align__(16) __nv_bfloat16 g_wphi[EMB * EMB];          // bf16 hi/lo, [n][k]
__device__ __align__(16) __nv_bfloat16 g_wplo[EMB * EMB];
__device__ __align__(16) __nv_bfloat16 g_atthi[BT * EMB];
__device__ __align__(16) __nv_bfloat16 g_attlo[BT * EMB];

// ---------------------------------------------------------------------------
// mma.sync / ldmatrix / cp.async helpers (sm_80-era; base compute_103-safe)
// ---------------------------------------------------------------------------
__device__ __forceinline__ uint32_t smem_u32(const void* p) {
    uint32_t a;
    asm("{ .reg .u64 t; cvta.to.shared.u64 t, %1; cvt.u32.u64 %0, t; }"
        : "=r"(a) : "l"(p));
    return a;
}
__device__ __forceinline__ void ldm4(uint32_t* r, uint32_t addr) {
    asm volatile("ldmatrix.sync.aligned.m8n8.x4.shared.b16 {%0,%1,%2,%3}, [%4];"
        : "=r"(r[0]), "=r"(r[1]), "=r"(r[2]), "=r"(r[3]) : "r"(addr));
}
__device__ __forceinline__ void ldm4t(uint32_t* r, uint32_t addr) {
    asm volatile("ldmatrix.sync.aligned.m8n8.x4.trans.shared.b16 {%0,%1,%2,%3}, [%4];"
        : "=r"(r[0]), "=r"(r[1]), "=r"(r[2]), "=r"(r[3]) : "r"(addr));
}
__device__ __forceinline__ void mma_bf16(float* c, const uint32_t* a, const uint32_t* b) {
    asm volatile(
        "mma.sync.aligned.m16n8k16.row.col.f32.bf16.bf16.f32 "
        "{%0,%1,%2,%3}, {%4,%5,%6,%7}, {%8,%9}, {%0,%1,%2,%3};"
        : "+f"(c[0]), "+f"(c[1]), "+f"(c[2]), "+f"(c[3])
        : "r"(a[0]), "r"(a[1]), "r"(a[2]), "r"(a[3]), "r"(b[0]), "r"(b[1]));
}
__device__ __forceinline__ void mma_f16(float* c, const uint32_t* a, const uint32_t* b) {
    asm volatile(
        "mma.sync.aligned.m16n8k16.row.col.f32.f16.f16.f32 "
        "{%0,%1,%2,%3}, {%4,%5,%6,%7}, {%8,%9}, {%0,%1,%2,%3};"
        : "+f"(c[0]), "+f"(c[1]), "+f"(c[2]), "+f"(c[3])
        : "r"(a[0]), "r"(a[1]), "r"(a[2]), "r"(a[3]), "r"(b[0]), "r"(b[1]));
}
__device__ __forceinline__ void cp16(uint32_t dst, const void* src) {
    asm volatile("cp.async.cg.shared.global [%0], [%1], 16;" :: "r"(dst), "l"(src));
}
#define CP_COMMIT() asm volatile("cp.async.commit_group;" ::: "memory")
#define CP_WAIT_2() asm volatile("cp.async.wait_group 2;" ::: "memory")
#define CP_WAIT_0() asm volatile("cp.async.wait_group 0;" ::: "memory")

// pack: low half = lo, high half = hi
__device__ __forceinline__ uint32_t pack_bf16x2(float lo, float hi) {
    uint32_t r;
    asm("cvt.rn.bf16x2.f32 %0, %1, %2;" : "=r"(r) : "f"(hi), "f"(lo));
    return r;
}
__device__ __forceinline__ uint32_t pack_resid(uint32_t u, float lo, float hi) {
    float flo = __uint_as_float(u << 16);
    float fhi = __uint_as_float(u & 0xffff0000u);
    return pack_bf16x2(lo - flo, hi - fhi);
}

// 64B-row tile swizzle (4 units of 16B): u ^ ((r>>1)&3) — conflict-free ldmatrix
__device__ __forceinline__ uint32_t swz(uint32_t r, uint32_t u) {
    return (r << 6) + ((u ^ ((r >> 1) & 3u)) << 4);
}
// 128B-row tile swizzle (8 units of 16B): u ^ (r&7)
__device__ __forceinline__ uint32_t swz8(uint32_t r, uint32_t u) {
    return (r << 7) + ((u ^ (r & 7u)) << 4);
}

// ---------------------------------------------------------------------------
// Prep kernels
// ---------------------------------------------------------------------------
__global__ void prep_x(const float* __restrict__ x) {
    int i = blockIdx.x * 256 + threadIdx.x;
    if (i < BT * EMB) {
        float v = x[i];
        __half h = __float2half(v);
        g_xhi[i] = h;
        g_xlo[i] = __float2half(v - __half2float(h));
    }
}
__global__ void prep_w(const float* __restrict__ wq, const float* __restrict__ wk,
                       const float* __restrict__ wv) {
    int i = blockIdx.x * 256 + threadIdx.x;
    if (i >= 3 * HH * DD * EMB) return;
    int e = i % EMB;
    int d = (i / EMB) % DD;
    int h = (i / (EMB * DD)) % HH;
    int z = i / (EMB * DD * HH);
    const float* w = (z == 0) ? wq : (z == 1) ? wk : wv;
    g_wthi[i] = __float2half(w[(h * EMB + e) * DD + d]);
}
__global__ void prep_wp(const float* __restrict__ wp) {
    int i = blockIdx.x * 256 + threadIdx.x;
    if (i >= EMB * EMB) return;
    int k = i % EMB;
    int n = i / EMB;
    float v = wp[k * EMB + n];
    __nv_bfloat16 hv = __float2bfloat16(v);
    g_wphi[i] = hv;
    g_wplo[i] = __float2bfloat16(v - __bfloat162float(hv));
}

// ---------------------------------------------------------------------------
// QKV GEMM v2: fp16 2-term (hiA*hiB + loA*hiB), cp.async 4-stage pipeline.
// CTA 128x128, warp tile 32x64, k-chunks of 32 (12 chunks over K=384).
// Stage = Ahi(8KB) + Alo(8KB) + Bhi(8KB) = 24KB; 4 stages = 96KB smem.
// Epilogue: bf16 hi/lo q/k/v (q pre-scaled 1/8) for the bf16 attention.
// ---------------------------------------------------------------------------
#define QST 24576
#define QOFF_AH 0
#define QOFF_AL 8192
#define QOFF_BH 16384

__device__ __forceinline__ void qkv_issue(char* smbase, int stg, int kc,
                                          int m0, int n0, int lr, int lu) {
    uint32_t s0 = smem_u32(smbase) + stg * QST;
    const char* A0 = (const char*)g_xhi;
    const char* A1 = (const char*)g_xlo;
    const char* B0 = (const char*)g_wthi;
    #pragma unroll
    for (int j = 0; j < 2; j++) {
        int r = lr + j * 64;
        size_t ga = (size_t)(m0 + r) * 768 + kc * 64 + lu * 16;
        size_t gb = (size_t)(n0 + r) * 768 + kc * 64 + lu * 16;
        cp16(s0 + QOFF_AH + swz(r, lu), A0 + ga);
        cp16(s0 + QOFF_AL + swz(r, lu), A1 + ga);
        cp16(s0 + QOFF_BH + swz(r, lu), B0 + gb);
    }
}

__global__ __launch_bounds__(256, 2) void qkv_tc2()
{
    extern __shared__ char sm[];
    const uint32_t sb = smem_u32(sm);
    const int tid  = threadIdx.x;
    const int wid  = tid >> 5;
    const int lane = tid & 31;
    const int m0   = blockIdx.y * 128;
    const int n0   = blockIdx.x * 128;
    const int lr   = tid >> 2;
    const int lu   = tid & 3;

    const int wm   = (wid >> 1) * 32;
    const int wn   = (wid & 1) * 64;
    const int a_r  = wm + (lane & 15);
    const int a_u0 = (lane >> 4);
    const int b_r  = wn + ((lane >> 4) & 1) * 8 + (lane & 7);
    const int b_u0 = (lane >> 3) & 1;

    qkv_issue(sm, 0, 0, m0, n0, lr, lu); CP_COMMIT();
    qkv_issue(sm, 1, 1, m0, n0, lr, lu); CP_COMMIT();
    qkv_issue(sm, 2, 2, m0, n0, lr, lu); CP_COMMIT();

    float c[2][8][4];
    #pragma unroll
    for (int mt = 0; mt < 2; mt++)
        #pragma unroll
        for (int nt = 0; nt < 8; nt++)
            #pragma unroll
            for (int q = 0; q < 4; q++) c[mt][nt][q] = 0.0f;

    for (int kc = 0; kc < 12; kc++) {
        CP_WAIT_2();
        __syncthreads();
        if (kc + 3 < 12) { qkv_issue(sm, (kc + 3) & 3, kc + 3, m0, n0, lr, lu); CP_COMMIT(); }

        const uint32_t base = sb + (kc & 3) * QST;
        #pragma unroll
        for (int ks = 0; ks < 2; ks++) {
            uint32_t ahi[2][4], alo[2][4], bhi[8][2];
            #pragma unroll
            for (int mt = 0; mt < 2; mt++) {
                uint32_t r = a_r + mt * 16;
                uint32_t u = ks * 2 + a_u0;
                ldm4(ahi[mt], base + QOFF_AH + swz(r, u));
                ldm4(alo[mt], base + QOFF_AL + swz(r, u));
            }
            #pragma unroll
            for (int p = 0; p < 4; p++) {
                uint32_t r = b_r + p * 16;
                uint32_t u = ks * 2 + b_u0;
                uint32_t t4[4];
                ldm4(t4, base + QOFF_BH + swz(r, u));
                bhi[2 * p][0] = t4[0]; bhi[2 * p][1] = t4[1];
                bhi[2 * p + 1][0] = t4[2]; bhi[2 * p + 1][1] = t4[3];
            }
            #pragma unroll
            for (int mt = 0; mt < 2; mt++)
                #pragma unroll
                for (int nt = 0; nt < 8; nt++) {
                    mma_f16(c[mt][nt], ahi[mt], bhi[nt]);
                    mma_f16(c[mt][nt], alo[mt], bhi[nt]);
                }
        }
    }

    // epilogue: bf16 hi/lo q/k/v (q scaled by 1/8)
    const int row0 = lane >> 2;
    const int col0 = (lane & 3) * 2;
    const int z = n0 / 384;
    const int nloc = n0 % 384;
    const float scl = (z == 0) ? 0.125f : 1.0f;
    __nv_bfloat16* dhi = (z == 0) ? g_qhi : (z == 1) ? g_khi : g_vhi;
    __nv_bfloat16* dlo = (z == 0) ? g_qlo : (z == 1) ? g_klo : g_vlo;
    #pragma unroll
    for (int mt = 0; mt < 2; mt++)
        #pragma unroll
        for (int half = 0; half < 2; half++) {
            int m = m0 + wm + mt * 16 + row0 + half * 8;
            int b = m >> 8, t = m & 255;
            #pragma unroll
            for (int nt = 0; nt < 8; nt++) {
                int n = nloc + wn + nt * 8 + col0;
                int h = n >> 6, d = n & 63;
                size_t idx = (((size_t)b * HH + h) * TT + t) * DD + d;
                float v0 = c[mt][nt][half * 2] * scl;
                float v1 = c[mt][nt][half * 2 + 1] * scl;
                uint32_t hp = pack_bf16x2(v0, v1);
                *(uint32_t*)(dhi + idx) = hp;
                *(uint32_t*)(dlo + idx) = pack_resid(hp, v0, v1);
            }
        }
}

// ---------------------------------------------------------------------------
// Output projection GEMM: bf16 3-term, double-buffered (R4-proven path)
// ---------------------------------------------------------------------------
#define ST_SZ   32768
#define OFF_AHI 0
#define OFF_ALO 8192
#define OFF_BHI 16384
#define OFF_BLO 24576

__global__ __launch_bounds__(256, 2) void gemm_proj(const float* __restrict__ bias,
                                                    float* __restrict__ outp)
{
    extern __shared__ char sm[];
    const uint32_t sb = smem_u32(sm);

    const char* AhiB = (const char*)g_atthi;
    const char* AloB = (const char*)g_attlo;
    const char* BhiB = (const char*)g_wphi;
    const char* BloB = (const char*)g_wplo;

    const int tid  = threadIdx.x;
    const int wid  = tid >> 5;
    const int lane = tid & 31;
    const int m0   = blockIdx.y * 128;
    const int n0   = blockIdx.x * 128;

    const int lr = tid >> 2;
    const int lu = tid & 3;

    const int wm = (wid >> 1) * 32;
    const int wn = (wid & 1) * 64;
    const int a_r  = wm + (lane & 15);
    const int a_u0 = (lane >> 4);
    const int b_r  = wn + ((lane >> 4) & 1) * 8 + (lane & 7);
    const int b_u0 = (lane >> 3) & 1;

    float c[2][8][4];
    #pragma unroll
    for (int mt = 0; mt < 2; mt++)
        #pragma unroll
        for (int nt = 0; nt < 8; nt++)
            #pragma unroll
            for (int q = 0; q < 4; q++) c[mt][nt][q] = 0.0f;

    {
        #pragma unroll
        for (int j = 0; j < 2; j++) {
            int r = lr + j * 64;
            size_t ga = (size_t)(m0 + r) * 768 + lu * 16;
            size_t gb = (size_t)(n0 + r) * 768 + lu * 16;
            *(uint4*)(sm + OFF_AHI + swz(r, lu)) = *(const uint4*)(AhiB + ga);
            *(uint4*)(sm + OFF_ALO + swz(r, lu)) = *(const uint4*)(AloB + ga);
            *(uint4*)(sm + OFF_BHI + swz(r, lu)) = *(const uint4*)(BhiB + gb);
            *(uint4*)(sm + OFF_BLO + swz(r, lu)) = *(const uint4*)(BloB + gb);
        }
    }
    __syncthreads();

    int stage = 0;
    for (int kc = 0; kc < 12; kc++) {
        uint4 v[8];
        if (kc < 11) {
            const int ko = (kc + 1) * 64;
            #pragma unroll
            for (int j = 0; j < 2; j++) {
                int r = lr + j * 64;
                size_t ga = (size_t)(m0 + r) * 768 + ko + lu * 16;
                size_t gb = (size_t)(n0 + r) * 768 + ko + lu * 16;
                v[j * 4 + 0] = *(const uint4*)(AhiB + ga);
                v[j * 4 + 1] = *(const uint4*)(AloB + ga);
                v[j * 4 + 2] = *(const uint4*)(BhiB + gb);
                v[j * 4 + 3] = *(const uint4*)(BloB + gb);
            }
        }

        const uint32_t base = sb + stage * ST_SZ;
        #pragma unroll
        for (int ks = 0; ks < 2; ks++) {
            uint32_t ahi[2][4], alo[2][4], bhi[8][2], blo[8][2];
            #pragma unroll
            for (int mt = 0; mt < 2; mt++) {
                uint32_t r = a_r + mt * 16;
                uint32_t u = ks * 2 + a_u0;
                ldm4(ahi[mt], base + OFF_AHI + swz(r, u));
                ldm4(alo[mt], base + OFF_ALO + swz(r, u));
            }
            #pragma unroll
            for (int p = 0; p < 4; p++) {
                uint32_t r = b_r + p * 16;
                uint32_t u = ks * 2 + b_u0;
                uint32_t t4[4];
                ldm4(t4, base + OFF_BHI + swz(r, u));
                bhi[2 * p][0] = t4[0]; bhi[2 * p][1] = t4[1];
                bhi[2 * p + 1][0] = t4[2]; bhi[2 * p + 1][1] = t4[3];
                ldm4(t4, base + OFF_BLO + swz(r, u));
                blo[2 * p][0] = t4[0]; blo[2 * p][1] = t4[1];
                blo[2 * p + 1][0] = t4[2]; blo[2 * p + 1][1] = t4[3];
            }
            #pragma unroll
            for (int mt = 0; mt < 2; mt++)
                #pragma unroll
                for (int nt = 0; nt < 8; nt++) {
                    mma_bf16(c[mt][nt], ahi[mt], bhi[nt]);
                    mma_bf16(c[mt][nt], alo[mt], bhi[nt]);
                    mma_bf16(c[mt][nt], ahi[mt], blo[nt]);
                }
        }

        if (kc < 11) {
            char* dst = sm + (stage ^ 1) * ST_SZ;
            #pragma unroll
            for (int j = 0; j < 2; j++) {
                int r = lr + j * 64;
                *(uint4*)(dst + OFF_AHI + swz(r, lu)) = v[j * 4 + 0];
                *(uint4*)(dst + OFF_ALO + swz(r, lu)) = v[j * 4 + 1];
                *(uint4*)(dst + OFF_BHI + swz(r, lu)) = v[j * 4 + 2];
                *(uint4*)(dst + OFF_BLO + swz(r, lu)) = v[j * 4 + 3];
            }
        }
        __syncthreads();
        stage ^= 1;
    }

    const int row0 = lane >> 2;
    const int col0 = (lane & 3) * 2;
    #pragma unroll
    for (int mt = 0; mt < 2; mt++)
        #pragma unroll
        for (int half = 0; half < 2; half++) {
            int m = m0 + wm + mt * 16 + row0 + half * 8;
            #pragma unroll
            for (int nt = 0; nt < 8; nt++) {
                int n = n0 + wn + nt * 8 + col0;
                float2 val = make_float2(c[mt][nt][half * 2] + bias[n],
                                         c[mt][nt][half * 2 + 1] + bias[n + 1]);
                *(float2*)(outp + (size_t)m * EMB + n) = val;
            }
        }
}

// ---------------------------------------------------------------------------
// Tensor-core causal flash attention (bf16 3-term, R4-proven), cp.async loads.
// ---------------------------------------------------------------------------
#define AQHI 0
#define AQLO 16384
#define AKHI 32768
#define AKLO 49152
#define AVHI 65536
#define AVLO 81920
#define ATT_SMEM 98304

__global__ __launch_bounds__(256) void attn_tc()
{
    extern __shared__ char sm[];
    const uint32_t sb = smem_u32(sm);
    const int qt  = blockIdx.x;
    const int bh  = blockIdx.y;
    const int tid = threadIdx.x;
    const int wid = tid >> 5;
    const int lane = tid & 31;

    const __nv_bfloat16* qhi = g_qhi + ((size_t)bh * TT + qt * 128) * DD;
    const __nv_bfloat16* qlo = g_qlo + ((size_t)bh * TT + qt * 128) * DD;
    const __nv_bfloat16* khi = g_khi + (size_t)bh * TT * DD;
    const __nv_bfloat16* klo = g_klo + (size_t)bh * TT * DD;
    const __nv_bfloat16* vhi = g_vhi + (size_t)bh * TT * DD;
    const __nv_bfloat16* vlo = g_vlo + (size_t)bh * TT * DD;

    // load Q hi/lo via cp.async
    #pragma unroll
    for (int j = 0; j < 8; j++) {
        int idx = tid + 256 * j;
        int arr = idx >> 10;
        int r = (idx >> 3) & 127;
        int u = idx & 7;
        const __nv_bfloat16* src = arr ? qlo : qhi;
        cp16(sb + (arr ? AQLO : AQHI) + swz8(r, u), src + (size_t)r * DD + u * 8);
    }
    CP_COMMIT();
    CP_WAIT_0();
    __syncthreads();

    // Q fragments (4 k-chunks of 16)
    uint32_t qfh[4][4], qfl[4][4];
    {
        int ar = wid * 16 + (lane & 15);
        #pragma unroll
        for (int kc = 0; kc < 4; kc++) {
            int u = kc * 2 + (lane >> 4);
            ldm4(qfh[kc], sb + AQHI + swz8(ar, u));
            ldm4(qfl[kc], sb + AQLO + swz8(ar, u));
        }
    }

    float o[8][4];
    #pragma unroll
    for (int nt = 0; nt < 8; nt++)
        #pragma unroll
        for (int q = 0; q < 4; q++) o[nt][q] = 0.0f;
    float mx[2] = {-1e30f, -1e30f};
    float lsum[2] = {0.0f, 0.0f};

    for (int kt = 0; kt <= qt; kt++) {
        __syncthreads();
        // load K/V tile hi/lo via cp.async
        #pragma unroll
        for (int j = 0; j < 16; j++) {
            int idx = tid + 256 * j;
            int arr = idx >> 10;
            int r = (idx >> 3) & 127;
            int u = idx & 7;
            const __nv_bfloat16* src = (arr == 0) ? khi : (arr == 1) ? klo
                                      : (arr == 2) ? vhi : vlo;
            cp16(sb + AKHI + arr * 16384 + swz8(r, u),
                 src + ((size_t)kt * 128 + r) * DD + u * 8);
        }
        CP_COMMIT();
        CP_WAIT_0();
        __syncthreads();

        // S = Q K^T
        float s[16][4];
        #pragma unroll
        for (int nt = 0; nt < 16; nt++)
            #pragma unroll
            for (int q = 0; q < 4; q++) s[nt][q] = 0.0f;

        #pragma unroll
        for (int np = 0; np < 8; np++) {
            int br = np * 16 + ((lane >> 4) & 1) * 8 + (lane & 7);
            #pragma unroll
            for (int kc = 0; kc < 4; kc++) {
                int u = kc * 2 + ((lane >> 3) & 1);
                uint32_t th[4], tl[4];
                ldm4(th, sb + AKHI + swz8(br, u));
                ldm4(tl, sb + AKLO + swz8(br, u));
                uint32_t b0h[2] = {th[0], th[1]}, b1h[2] = {th[2], th[3]};
                uint32_t b0l[2] = {tl[0], tl[1]}, b1l[2] = {tl[2], tl[3]};
                mma_bf16(s[2 * np], qfh[kc], b0h);
                mma_bf16(s[2 * np], qfl[kc], b0h);
                mma_bf16(s[2 * np], qfh[kc], b0l);
                mma_bf16(s[2 * np + 1], qfh[kc], b1h);
                mma_bf16(s[2 * np + 1], qfl[kc], b1h);
                mma_bf16(s[2 * np + 1], qfh[kc], b1l);
            }
        }

        // causal mask on diagonal tile
        if (kt == qt) {
            #pragma unroll
            for (int nt = 0; nt < 16; nt++)
                #pragma unroll
                for (int q = 0; q < 4; q++) {
                    int col = nt * 8 + (lane & 3) * 2 + (q & 1);
                    int row = wid * 16 + (lane >> 2) + (q >> 1) * 8;
                    if (col > row) s[nt][q] = -1e30f;
                }
        }

        // online softmax (two row-halves per lane)
        float al[2];
        #pragma unroll
        for (int hf = 0; hf < 2; hf++) {
            float rm = -1e30f;
            #pragma unroll
            for (int nt = 0; nt < 16; nt++)
                rm = fmaxf(rm, fmaxf(s[nt][hf * 2], s[nt][hf * 2 + 1]));
            rm = fmaxf(rm, __shfl_xor_sync(0xffffffffu, rm, 1));
            rm = fmaxf(rm, __shfl_xor_sync(0xffffffffu, rm, 2));
            float mn = fmaxf(mx[hf], rm);
            al[hf] = __expf(mx[hf] - mn);
            mx[hf] = mn;
            float ps = 0.0f;
            #pragma unroll
            for (int nt = 0; nt < 16; nt++) {
                s[nt][hf * 2]     = __expf(s[nt][hf * 2] - mn);
                s[nt][hf * 2 + 1] = __expf(s[nt][hf * 2 + 1] - mn);
                ps += s[nt][hf * 2] + s[nt][hf * 2 + 1];
            }
            ps += __shfl_xor_sync(0xffffffffu, ps, 1);
            ps += __shfl_xor_sync(0xffffffffu, ps, 2);
            lsum[hf] = lsum[hf] * al[hf] + ps;
        }
        #pragma unroll
        for (int nt = 0; nt < 8; nt++) {
            o[nt][0] *= al[0]; o[nt][1] *= al[0];
            o[nt][2] *= al[1]; o[nt][3] *= al[1];
        }

        // O += P V
        #pragma unroll
        for (int kc = 0; kc < 8; kc++) {
            uint32_t ah[4], alo4[4];
            ah[0] = pack_bf16x2(s[2 * kc][0], s[2 * kc][1]);
            ah[1] = pack_bf16x2(s[2 * kc][2], s[2 * kc][3]);
            ah[2] = pack_bf16x2(s[2 * kc + 1][0], s[2 * kc + 1][1]);
            ah[3] = pack_bf16x2(s[2 * kc + 1][2], s[2 * kc + 1][3]);
            alo4[0] = pack_resid(ah[0], s[2 * kc][0], s[2 * kc][1]);
            alo4[1] = pack_resid(ah[1], s[2 * kc][2], s[2 * kc][3]);
            alo4[2] = pack_resid(ah[2], s[2 * kc + 1][0], s[2 * kc + 1][1]);
            alo4[3] = pack_resid(ah[3], s[2 * kc + 1][2], s[2 * kc + 1][3]);

            int vr = kc * 16 + ((lane >> 3) & 1) * 8 + (lane & 7);
            #pragma unroll
            for (int ntp = 0; ntp < 4; ntp++) {
                int u = ntp * 2 + (lane >> 4);
                uint32_t th[4], tl[4];
                ldm4t(th, sb + AVHI + swz8(vr, u));
                ldm4t(tl, sb + AVLO + swz8(vr, u));
                uint32_t b0h[2] = {th[0], th[1]}, b1h[2] = {th[2], th[3]};
                uint32_t b0l[2] = {tl[0], tl[1]}, b1l[2] = {tl[2], tl[3]};
                mma_bf16(o[2 * ntp], ah, b0h);
                mma_bf16(o[2 * ntp], alo4, b0h);
                mma_bf16(o[2 * ntp], ah, b0l);
                mma_bf16(o[2 * ntp + 1], ah, b1h);
                mma_bf16(o[2 * ntp + 1], alo4, b1h);
                mma_bf16(o[2 * ntp + 1], ah, b1l);
            }
        }
    }

    // epilogue: normalize, write bf16 hi/lo att rows [BT][EMB]
    const int b = bh / HH, h = bh % HH;
    #pragma unroll
    for (int hf = 0; hf < 2; hf++) {
        float inv = 1.0f / lsum[hf];
        int t = qt * 128 + wid * 16 + (lane >> 2) + hf * 8;
        size_t rowb = ((size_t)b * TT + t) * EMB + h * 64 + (lane & 3) * 2;
        #pragma unroll
        for (int nt = 0; nt < 8; nt++) {
            float v0 = o[nt][hf * 2] * inv;
            float v1 = o[nt][hf * 2 + 1] * inv;
            uint32_t hp = pack_bf16x2(v0, v1);
            *(uint32_t*)(g_atthi + rowb + nt * 8) = hp;
            *(uint32_t*)(g_attlo + rowb + nt * 8) = pack_resid(hp, v0, v1);
        }
    }
}

// ---------------------------------------------------------------------------
extern "C" void kernel_launch(void* const* d_in, const int* in_sizes, int n_in,
                              void* d_out, int out_size)
{
    const float* x      = (const float*)d_in[0];
    const float* wq     = (const float*)d_in[1];
    const float* wk     = (const float*)d_in[2];
    const float* wv     = (const float*)d_in[3];
    const float* w_proj = (const float*)d_in[4];
    const float* b_proj = (const float*)d_in[5];
    float* out = (float*)d_out;

    cudaFuncSetAttribute(qkv_tc2, cudaFuncAttributeMaxDynamicSharedMemorySize, 4 * QST);
    cudaFuncSetAttribute(gemm_proj, cudaFuncAttributeMaxDynamicSharedMemorySize, 2 * ST_SZ);
    cudaFuncSetAttribute(attn_tc, cudaFuncAttributeMaxDynamicSharedMemorySize, ATT_SMEM);

    prep_x<<<(BT * EMB + 255) / 256, 256>>>(x);
    prep_w<<<(3 * HH * DD * EMB + 255) / 256, 256>>>(wq, wk, wv);
    prep_wp<<<(EMB * EMB + 255) / 256, 256>>>(w_proj);

    qkv_tc2<<<dim3(1152 / 128, BT / 128), 256, 4 * QST>>>();
    attn_tc<<<dim3(TT / 128, BB * HH), 256, ATT_SMEM>>>();
    gemm_proj<<<dim3(EMB / 128, BT / 128), 256, 2 * ST_SZ>>>(b_proj, out);
}

// round 6
// speedup vs baseline: 1.3431x; 1.3431x over previous
#include <cuda_runtime.h>
#include <cuda_bf16.h>
#include <cuda_fp16.h>
#include <cstdint>

#define BB 256
#define TT 256
#define EMB 384
#define HH 6
#define DD 64
#define BT (BB*TT)

// ---------------------------------------------------------------------------
// Scratch (__device__ globals — allocation-free rule)
// ---------------------------------------------------------------------------
__device__ __align__(16) __nv_bfloat16 g_qhi[BB * HH * TT * DD];
__device__ __align__(16) __nv_bfloat16 g_qlo[BB * HH * TT * DD];
__device__ __align__(16) __nv_bfloat16 g_khi[BB * HH * TT * DD];
__device__ __align__(16) __nv_bfloat16 g_klo[BB * HH * TT * DD];
__device__ __align__(16) __nv_bfloat16 g_vhi[BB * HH * TT * DD];
__device__ __align__(16) __nv_bfloat16 g_vlo[BB * HH * TT * DD];
__device__ __align__(16) __half        g_xhi[BT * EMB];            // fp16 split of x
__device__ __align__(16) __half        g_xlo[BT * EMB];
__device__ __align__(16) __half        g_wthi[3 * HH * DD * EMB];  // fp16 hi, [n=z*384+h*64+d][e]
__device__ __align__(16) __nv_bfloat16 g_wphi[EMB * EMB];          // bf16 hi/lo, [n][k]
__device__ __align__(16) __nv_bfloat16 g_wplo[EMB * EMB];
__device__ __align__(16) __nv_bfloat16 g_atthi[BT * EMB];
__device__ __align__(16) __nv_bfloat16 g_attlo[BT * EMB];

// ---------------------------------------------------------------------------
// mma.sync / ldmatrix helpers (sm_80-era; base compute_103-safe)
// ---------------------------------------------------------------------------
__device__ __forceinline__ uint32_t smem_u32(const void* p) {
    uint32_t a;
    asm("{ .reg .u64 t; cvta.to.shared.u64 t, %1; cvt.u32.u64 %0, t; }"
        : "=r"(a) : "l"(p));
    return a;
}
__device__ __forceinline__ void ldm4(uint32_t* r, uint32_t addr) {
    asm volatile("ldmatrix.sync.aligned.m8n8.x4.shared.b16 {%0,%1,%2,%3}, [%4];"
        : "=r"(r[0]), "=r"(r[1]), "=r"(r[2]), "=r"(r[3]) : "r"(addr));
}
__device__ __forceinline__ void ldm4t(uint32_t* r, uint32_t addr) {
    asm volatile("ldmatrix.sync.aligned.m8n8.x4.trans.shared.b16 {%0,%1,%2,%3}, [%4];"
        : "=r"(r[0]), "=r"(r[1]), "=r"(r[2]), "=r"(r[3]) : "r"(addr));
}
__device__ __forceinline__ void mma_bf16(float* c, const uint32_t* a, const uint32_t* b) {
    asm volatile(
        "mma.sync.aligned.m16n8k16.row.col.f32.bf16.bf16.f32 "
        "{%0,%1,%2,%3}, {%4,%5,%6,%7}, {%8,%9}, {%0,%1,%2,%3};"
        : "+f"(c[0]), "+f"(c[1]), "+f"(c[2]), "+f"(c[3])
        : "r"(a[0]), "r"(a[1]), "r"(a[2]), "r"(a[3]), "r"(b[0]), "r"(b[1]));
}
__device__ __forceinline__ void mma_f16(float* c, const uint32_t* a, const uint32_t* b) {
    asm volatile(
        "mma.sync.aligned.m16n8k16.row.col.f32.f16.f16.f32 "
        "{%0,%1,%2,%3}, {%4,%5,%6,%7}, {%8,%9}, {%0,%1,%2,%3};"
        : "+f"(c[0]), "+f"(c[1]), "+f"(c[2]), "+f"(c[3])
        : "r"(a[0]), "r"(a[1]), "r"(a[2]), "r"(a[3]), "r"(b[0]), "r"(b[1]));
}
// pack: low half = lo, high half = hi
__device__ __forceinline__ uint32_t pack_bf16x2(float lo, float hi) {
    uint32_t r;
    asm("cvt.rn.bf16x2.f32 %0, %1, %2;" : "=r"(r) : "f"(hi), "f"(lo));
    return r;
}
__device__ __forceinline__ uint32_t pack_resid(uint32_t u, float lo, float hi) {
    float flo = __uint_as_float(u << 16);
    float fhi = __uint_as_float(u & 0xffff0000u);
    return pack_bf16x2(lo - flo, hi - fhi);
}

// 64B-row tile swizzle (4 units of 16B): u ^ ((r>>1)&3)
__device__ __forceinline__ uint32_t swz(uint32_t r, uint32_t u) {
    return (r << 6) + ((u ^ ((r >> 1) & 3u)) << 4);
}
// 128B-row tile swizzle (8 units of 16B): u ^ (r&7)
__device__ __forceinline__ uint32_t swz8(uint32_t r, uint32_t u) {
    return (r << 7) + ((u ^ (r & 7u)) << 4);
}

// ---------------------------------------------------------------------------
// Prep kernels
// ---------------------------------------------------------------------------
__global__ void prep_x(const float* __restrict__ x) {
    int i = blockIdx.x * 256 + threadIdx.x;
    if (i < BT * EMB) {
        float v = x[i];
        __half h = __float2half(v);
        g_xhi[i] = h;
        g_xlo[i] = __float2half(v - __half2float(h));
    }
}
__global__ void prep_w(const float* __restrict__ wq, const float* __restrict__ wk,
                       const float* __restrict__ wv) {
    int i = blockIdx.x * 256 + threadIdx.x;
    if (i >= 3 * HH * DD * EMB) return;
    int e = i % EMB;
    int d = (i / EMB) % DD;
    int h = (i / (EMB * DD)) % HH;
    int z = i / (EMB * DD * HH);
    const float* w = (z == 0) ? wq : (z == 1) ? wk : wv;
    g_wthi[i] = __float2half(w[(h * EMB + e) * DD + d]);
}
__global__ void prep_wp(const float* __restrict__ wp) {
    int i = blockIdx.x * 256 + threadIdx.x;
    if (i >= EMB * EMB) return;
    int k = i % EMB;
    int n = i / EMB;
    float v = wp[k * EMB + n];
    __nv_bfloat16 hv = __float2bfloat16(v);
    g_wphi[i] = hv;
    g_wplo[i] = __float2bfloat16(v - __bfloat162float(hv));
}

// ---------------------------------------------------------------------------
// QKV GEMM v3: fp16 2-term, R4-proven double-buffer + register-prefetch.
// CTA 128x128, warp tile 32x64, 12 k-chunks of 32.
// Stage = Ahi(8KB)+Alo(8KB)+Bhi(8KB) = 24KB; 2 stages = 48KB.
// ---------------------------------------------------------------------------
#define QST 24576
#define QOFF_AH 0
#define QOFF_AL 8192
#define QOFF_BH 16384

__global__ __launch_bounds__(256, 2) void qkv_tc3()
{
    extern __shared__ char sm[];
    const uint32_t sb = smem_u32(sm);

    const char* AhiB = (const char*)g_xhi;
    const char* AloB = (const char*)g_xlo;
    const char* BhiB = (const char*)g_wthi;

    const int tid  = threadIdx.x;
    const int wid  = tid >> 5;
    const int lane = tid & 31;
    const int m0   = blockIdx.y * 128;
    const int n0   = blockIdx.x * 128;

    const int lr = tid >> 2;
    const int lu = tid & 3;

    const int wm   = (wid >> 1) * 32;
    const int wn   = (wid & 1) * 64;
    const int a_r  = wm + (lane & 15);
    const int a_u0 = (lane >> 4);
    const int b_r  = wn + ((lane >> 4) & 1) * 8 + (lane & 7);
    const int b_u0 = (lane >> 3) & 1;

    float c[2][8][4];
    #pragma unroll
    for (int mt = 0; mt < 2; mt++)
        #pragma unroll
        for (int nt = 0; nt < 8; nt++)
            #pragma unroll
            for (int q = 0; q < 4; q++) c[mt][nt][q] = 0.0f;

    // prologue: chunk 0 -> stage 0
    {
        #pragma unroll
        for (int j = 0; j < 2; j++) {
            int r = lr + j * 64;
            size_t ga = (size_t)(m0 + r) * 768 + lu * 16;
            size_t gb = (size_t)(n0 + r) * 768 + lu * 16;
            *(uint4*)(sm + QOFF_AH + swz(r, lu)) = *(const uint4*)(AhiB + ga);
            *(uint4*)(sm + QOFF_AL + swz(r, lu)) = *(const uint4*)(AloB + ga);
            *(uint4*)(sm + QOFF_BH + swz(r, lu)) = *(const uint4*)(BhiB + gb);
        }
    }
    __syncthreads();

    int stage = 0;
    for (int kc = 0; kc < 12; kc++) {
        uint4 v[6];
        if (kc < 11) {
            const int ko = (kc + 1) * 64;
            #pragma unroll
            for (int j = 0; j < 2; j++) {
                int r = lr + j * 64;
                size_t ga = (size_t)(m0 + r) * 768 + ko + lu * 16;
                size_t gb = (size_t)(n0 + r) * 768 + ko + lu * 16;
                v[j * 3 + 0] = *(const uint4*)(AhiB + ga);
                v[j * 3 + 1] = *(const uint4*)(AloB + ga);
                v[j * 3 + 2] = *(const uint4*)(BhiB + gb);
            }
        }

        const uint32_t base = sb + stage * QST;
        #pragma unroll
        for (int ks = 0; ks < 2; ks++) {
            uint32_t ahi[2][4], alo[2][4], bhi[8][2];
            #pragma unroll
            for (int mt = 0; mt < 2; mt++) {
                uint32_t r = a_r + mt * 16;
                uint32_t u = ks * 2 + a_u0;
                ldm4(ahi[mt], base + QOFF_AH + swz(r, u));
                ldm4(alo[mt], base + QOFF_AL + swz(r, u));
            }
            #pragma unroll
            for (int p = 0; p < 4; p++) {
                uint32_t r = b_r + p * 16;
                uint32_t u = ks * 2 + b_u0;
                uint32_t t4[4];
                ldm4(t4, base + QOFF_BH + swz(r, u));
                bhi[2 * p][0] = t4[0]; bhi[2 * p][1] = t4[1];
                bhi[2 * p + 1][0] = t4[2]; bhi[2 * p + 1][1] = t4[3];
            }
            #pragma unroll
            for (int mt = 0; mt < 2; mt++)
                #pragma unroll
                for (int nt = 0; nt < 8; nt++) {
                    mma_f16(c[mt][nt], ahi[mt], bhi[nt]);
                    mma_f16(c[mt][nt], alo[mt], bhi[nt]);
                }
        }

        if (kc < 11) {
            char* dst = sm + (stage ^ 1) * QST;
            #pragma unroll
            for (int j = 0; j < 2; j++) {
                int r = lr + j * 64;
                *(uint4*)(dst + QOFF_AH + swz(r, lu)) = v[j * 3 + 0];
                *(uint4*)(dst + QOFF_AL + swz(r, lu)) = v[j * 3 + 1];
                *(uint4*)(dst + QOFF_BH + swz(r, lu)) = v[j * 3 + 2];
            }
        }
        __syncthreads();
        stage ^= 1;
    }

    // epilogue: bf16 hi/lo q/k/v (q scaled by 1/8)
    const int row0 = lane >> 2;
    const int col0 = (lane & 3) * 2;
    const int z = n0 / 384;
    const int nloc = n0 % 384;
    const float scl = (z == 0) ? 0.125f : 1.0f;
    __nv_bfloat16* dhi = (z == 0) ? g_qhi : (z == 1) ? g_khi : g_vhi;
    __nv_bfloat16* dlo = (z == 0) ? g_qlo : (z == 1) ? g_klo : g_vlo;
    #pragma unroll
    for (int mt = 0; mt < 2; mt++)
        #pragma unroll
        for (int half = 0; half < 2; half++) {
            int m = m0 + wm + mt * 16 + row0 + half * 8;
            int b = m >> 8, t = m & 255;
            #pragma unroll
            for (int nt = 0; nt < 8; nt++) {
                int n = nloc + wn + nt * 8 + col0;
                int h = n >> 6, d = n & 63;
                size_t idx = (((size_t)b * HH + h) * TT + t) * DD + d;
                float v0 = c[mt][nt][half * 2] * scl;
                float v1 = c[mt][nt][half * 2 + 1] * scl;
                uint32_t hp = pack_bf16x2(v0, v1);
                *(uint32_t*)(dhi + idx) = hp;
                *(uint32_t*)(dlo + idx) = pack_resid(hp, v0, v1);
            }
        }
}

// ---------------------------------------------------------------------------
// Output projection GEMM: bf16 3-term, double-buffered (R4-proven)
// ---------------------------------------------------------------------------
#define ST_SZ   32768
#define OFF_AHI 0
#define OFF_ALO 8192
#define OFF_BHI 16384
#define OFF_BLO 24576

__global__ __launch_bounds__(256, 2) void gemm_proj(const float* __restrict__ bias,
                                                    float* __restrict__ outp)
{
    extern __shared__ char sm[];
    const uint32_t sb = smem_u32(sm);

    const char* AhiB = (const char*)g_atthi;
    const char* AloB = (const char*)g_attlo;
    const char* BhiB = (const char*)g_wphi;
    const char* BloB = (const char*)g_wplo;

    const int tid  = threadIdx.x;
    const int wid  = tid >> 5;
    const int lane = tid & 31;
    const int m0   = blockIdx.y * 128;
    const int n0   = blockIdx.x * 128;

    const int lr = tid >> 2;
    const int lu = tid & 3;

    const int wm = (wid >> 1) * 32;
    const int wn = (wid & 1) * 64;
    const int a_r  = wm + (lane & 15);
    const int a_u0 = (lane >> 4);
    const int b_r  = wn + ((lane >> 4) & 1) * 8 + (lane & 7);
    const int b_u0 = (lane >> 3) & 1;

    float c[2][8][4];
    #pragma unroll
    for (int mt = 0; mt < 2; mt++)
        #pragma unroll
        for (int nt = 0; nt < 8; nt++)
            #pragma unroll
            for (int q = 0; q < 4; q++) c[mt][nt][q] = 0.0f;

    {
        #pragma unroll
        for (int j = 0; j < 2; j++) {
            int r = lr + j * 64;
            size_t ga = (size_t)(m0 + r) * 768 + lu * 16;
            size_t gb = (size_t)(n0 + r) * 768 + lu * 16;
            *(uint4*)(sm + OFF_AHI + swz(r, lu)) = *(const uint4*)(AhiB + ga);
            *(uint4*)(sm + OFF_ALO + swz(r, lu)) = *(const uint4*)(AloB + ga);
            *(uint4*)(sm + OFF_BHI + swz(r, lu)) = *(const uint4*)(BhiB + gb);
            *(uint4*)(sm + OFF_BLO + swz(r, lu)) = *(const uint4*)(BloB + gb);
        }
    }
    __syncthreads();

    int stage = 0;
    for (int kc = 0; kc < 12; kc++) {
        uint4 v[8];
        if (kc < 11) {
            const int ko = (kc + 1) * 64;
            #pragma unroll
            for (int j = 0; j < 2; j++) {
                int r = lr + j * 64;
                size_t ga = (size_t)(m0 + r) * 768 + ko + lu * 16;
                size_t gb = (size_t)(n0 + r) * 768 + ko + lu * 16;
                v[j * 4 + 0] = *(const uint4*)(AhiB + ga);
                v[j * 4 + 1] = *(const uint4*)(AloB + ga);
                v[j * 4 + 2] = *(const uint4*)(BhiB + gb);
                v[j * 4 + 3] = *(const uint4*)(BloB + gb);
            }
        }

        const uint32_t base = sb + stage * ST_SZ;
        #pragma unroll
        for (int ks = 0; ks < 2; ks++) {
            uint32_t ahi[2][4], alo[2][4], bhi[8][2], blo[8][2];
            #pragma unroll
            for (int mt = 0; mt < 2; mt++) {
                uint32_t r = a_r + mt * 16;
                uint32_t u = ks * 2 + a_u0;
                ldm4(ahi[mt], base + OFF_AHI + swz(r, u));
                ldm4(alo[mt], base + OFF_ALO + swz(r, u));
            }
            #pragma unroll
            for (int p = 0; p < 4; p++) {
                uint32_t r = b_r + p * 16;
                uint32_t u = ks * 2 + b_u0;
                uint32_t t4[4];
                ldm4(t4, base + OFF_BHI + swz(r, u));
                bhi[2 * p][0] = t4[0]; bhi[2 * p][1] = t4[1];
                bhi[2 * p + 1][0] = t4[2]; bhi[2 * p + 1][1] = t4[3];
                ldm4(t4, base + OFF_BLO + swz(r, u));
                blo[2 * p][0] = t4[0]; blo[2 * p][1] = t4[1];
                blo[2 * p + 1][0] = t4[2]; blo[2 * p + 1][1] = t4[3];
            }
            #pragma unroll
            for (int mt = 0; mt < 2; mt++)
                #pragma unroll
                for (int nt = 0; nt < 8; nt++) {
                    mma_bf16(c[mt][nt], ahi[mt], bhi[nt]);
                    mma_bf16(c[mt][nt], alo[mt], bhi[nt]);
                    mma_bf16(c[mt][nt], ahi[mt], blo[nt]);
                }
        }

        if (kc < 11) {
            char* dst = sm + (stage ^ 1) * ST_SZ;
            #pragma unroll
            for (int j = 0; j < 2; j++) {
                int r = lr + j * 64;
                *(uint4*)(dst + OFF_AHI + swz(r, lu)) = v[j * 4 + 0];
                *(uint4*)(dst + OFF_ALO + swz(r, lu)) = v[j * 4 + 1];
                *(uint4*)(dst + OFF_BHI + swz(r, lu)) = v[j * 4 + 2];
                *(uint4*)(dst + OFF_BLO + swz(r, lu)) = v[j * 4 + 3];
            }
        }
        __syncthreads();
        stage ^= 1;
    }

    const int row0 = lane >> 2;
    const int col0 = (lane & 3) * 2;
    #pragma unroll
    for (int mt = 0; mt < 2; mt++)
        #pragma unroll
        for (int half = 0; half < 2; half++) {
            int m = m0 + wm + mt * 16 + row0 + half * 8;
            #pragma unroll
            for (int nt = 0; nt < 8; nt++) {
                int n = n0 + wn + nt * 8 + col0;
                float2 val = make_float2(c[mt][nt][half * 2] + bias[n],
                                         c[mt][nt][half * 2 + 1] + bias[n + 1]);
                *(float2*)(outp + (size_t)m * EMB + n) = val;
            }
        }
}

// ---------------------------------------------------------------------------
// Tensor-core causal flash attention — exact R4-proven version (LDG/STS).
// ---------------------------------------------------------------------------
#define AQHI 0
#define AQLO 16384
#define AKHI 32768
#define AKLO 49152
#define AVHI 65536
#define AVLO 81920
#define ATT_SMEM 98304

__global__ __launch_bounds__(256) void attn_tc()
{
    extern __shared__ char sm[];
    const uint32_t sb = smem_u32(sm);
    const int qt  = blockIdx.x;
    const int bh  = blockIdx.y;
    const int tid = threadIdx.x;
    const int wid = tid >> 5;
    const int lane = tid & 31;

    const __nv_bfloat16* qhi = g_qhi + ((size_t)bh * TT + qt * 128) * DD;
    const __nv_bfloat16* qlo = g_qlo + ((size_t)bh * TT + qt * 128) * DD;
    const __nv_bfloat16* khi = g_khi + (size_t)bh * TT * DD;
    const __nv_bfloat16* klo = g_klo + (size_t)bh * TT * DD;
    const __nv_bfloat16* vhi = g_vhi + (size_t)bh * TT * DD;
    const __nv_bfloat16* vlo = g_vlo + (size_t)bh * TT * DD;

    // load Q hi/lo
    #pragma unroll
    for (int j = 0; j < 8; j++) {
        int idx = tid + 256 * j;
        int arr = idx >> 10;
        int r = (idx >> 3) & 127;
        int u = idx & 7;
        const __nv_bfloat16* src = arr ? qlo : qhi;
        *(uint4*)(sm + (arr ? AQLO : AQHI) + swz8(r, u)) =
            *(const uint4*)(src + (size_t)r * DD + u * 8);
    }
    __syncthreads();

    uint32_t qfh[4][4], qfl[4][4];
    {
        int ar = wid * 16 + (lane & 15);
        #pragma unroll
        for (int kc = 0; kc < 4; kc++) {
            int u = kc * 2 + (lane >> 4);
            ldm4(qfh[kc], sb + AQHI + swz8(ar, u));
            ldm4(qfl[kc], sb + AQLO + swz8(ar, u));
        }
    }

    float o[8][4];
    #pragma unroll
    for (int nt = 0; nt < 8; nt++)
        #pragma unroll
        for (int q = 0; q < 4; q++) o[nt][q] = 0.0f;
    float mx[2] = {-1e30f, -1e30f};
    float lsum[2] = {0.0f, 0.0f};

    for (int kt = 0; kt <= qt; kt++) {
        __syncthreads();
        #pragma unroll
        for (int j = 0; j < 16; j++) {
            int idx = tid + 256 * j;
            int arr = idx >> 10;
            int r = (idx >> 3) & 127;
            int u = idx & 7;
            const __nv_bfloat16* src = (arr == 0) ? khi : (arr == 1) ? klo
                                      : (arr == 2) ? vhi : vlo;
            *(uint4*)(sm + AKHI + arr * 16384 + swz8(r, u)) =
                *(const uint4*)(src + ((size_t)kt * 128 + r) * DD + u * 8);
        }
        __syncthreads();

        float s[16][4];
        #pragma unroll
        for (int nt = 0; nt < 16; nt++)
            #pragma unroll
            for (int q = 0; q < 4; q++) s[nt][q] = 0.0f;

        #pragma unroll
        for (int np = 0; np < 8; np++) {
            int br = np * 16 + ((lane >> 4) & 1) * 8 + (lane & 7);
            #pragma unroll
            for (int kc = 0; kc < 4; kc++) {
                int u = kc * 2 + ((lane >> 3) & 1);
                uint32_t th[4], tl[4];
                ldm4(th, sb + AKHI + swz8(br, u));
                ldm4(tl, sb + AKLO + swz8(br, u));
                uint32_t b0h[2] = {th[0], th[1]}, b1h[2] = {th[2], th[3]};
                uint32_t b0l[2] = {tl[0], tl[1]}, b1l[2] = {tl[2], tl[3]};
                mma_bf16(s[2 * np], qfh[kc], b0h);
                mma_bf16(s[2 * np], qfl[kc], b0h);
                mma_bf16(s[2 * np], qfh[kc], b0l);
                mma_bf16(s[2 * np + 1], qfh[kc], b1h);
                mma_bf16(s[2 * np + 1], qfl[kc], b1h);
                mma_bf16(s[2 * np + 1], qfh[kc], b1l);
            }
        }

        if (kt == qt) {
            #pragma unroll
            for (int nt = 0; nt < 16; nt++)
                #pragma unroll
                for (int q = 0; q < 4; q++) {
                    int col = nt * 8 + (lane & 3) * 2 + (q & 1);
                    int row = wid * 16 + (lane >> 2) + (q >> 1) * 8;
                    if (col > row) s[nt][q] = -1e30f;
                }
        }

        float al[2];
        #pragma unroll
        for (int hf = 0; hf < 2; hf++) {
            float rm = -1e30f;
            #pragma unroll
            for (int nt = 0; nt < 16; nt++)
                rm = fmaxf(rm, fmaxf(s[nt][hf * 2], s[nt][hf * 2 + 1]));
            rm = fmaxf(rm, __shfl_xor_sync(0xffffffffu, rm, 1));
            rm = fmaxf(rm, __shfl_xor_sync(0xffffffffu, rm, 2));
            float mn = fmaxf(mx[hf], rm);
            al[hf] = __expf(mx[hf] - mn);
            mx[hf] = mn;
            float ps = 0.0f;
            #pragma unroll
            for (int nt = 0; nt < 16; nt++) {
                s[nt][hf * 2]     = __expf(s[nt][hf * 2] - mn);
                s[nt][hf * 2 + 1] = __expf(s[nt][hf * 2 + 1] - mn);
                ps += s[nt][hf * 2] + s[nt][hf * 2 + 1];
            }
            ps += __shfl_xor_sync(0xffffffffu, ps, 1);
            ps += __shfl_xor_sync(0xffffffffu, ps, 2);
            lsum[hf] = lsum[hf] * al[hf] + ps;
        }
        #pragma unroll
        for (int nt = 0; nt < 8; nt++) {
            o[nt][0] *= al[0]; o[nt][1] *= al[0];
            o[nt][2] *= al[1]; o[nt][3] *= al[1];
        }

        #pragma unroll
        for (int kc = 0; kc < 8; kc++) {
            uint32_t ah[4], alo4[4];
            ah[0] = pack_bf16x2(s[2 * kc][0], s[2 * kc][1]);
            ah[1] = pack_bf16x2(s[2 * kc][2], s[2 * kc][3]);
            ah[2] = pack_bf16x2(s[2 * kc + 1][0], s[2 * kc + 1][1]);
            ah[3] = pack_bf16x2(s[2 * kc + 1][2], s[2 * kc + 1][3]);
            alo4[0] = pack_resid(ah[0], s[2 * kc][0], s[2 * kc][1]);
            alo4[1] = pack_resid(ah[1], s[2 * kc][2], s[2 * kc][3]);
            alo4[2] = pack_resid(ah[2], s[2 * kc + 1][0], s[2 * kc + 1][1]);
            alo4[3] = pack_resid(ah[3], s[2 * kc + 1][2], s[2 * kc + 1][3]);

            int vr = kc * 16 + ((lane >> 3) & 1) * 8 + (lane & 7);
            #pragma unroll
            for (int ntp = 0; ntp < 4; ntp++) {
                int u = ntp * 2 + (lane >> 4);
                uint32_t th[4], tl[4];
                ldm4t(th, sb + AVHI + swz8(vr, u));
                ldm4t(tl, sb + AVLO + swz8(vr, u));
                uint32_t b0h[2] = {th[0], th[1]}, b1h[2] = {th[2], th[3]};
                uint32_t b0l[2] = {tl[0], tl[1]}, b1l[2] = {tl[2], tl[3]};
                mma_bf16(o[2 * ntp], ah, b0h);
                mma_bf16(o[2 * ntp], alo4, b0h);
                mma_bf16(o[2 * ntp], ah, b0l);
                mma_bf16(o[2 * ntp + 1], ah, b1h);
                mma_bf16(o[2 * ntp + 1], alo4, b1h);
                mma_bf16(o[2 * ntp + 1], ah, b1l);
            }
        }
    }

    const int b = bh / HH, h = bh % HH;
    #pragma unroll
    for (int hf = 0; hf < 2; hf++) {
        float inv = 1.0f / lsum[hf];
        int t = qt * 128 + wid * 16 + (lane >> 2) + hf * 8;
        size_t rowb = ((size_t)b * TT + t) * EMB + h * 64 + (lane & 3) * 2;
        #pragma unroll
        for (int nt = 0; nt < 8; nt++) {
            float v0 = o[nt][hf * 2] * inv;
            float v1 = o[nt][hf * 2 + 1] * inv;
            uint32_t hp = pack_bf16x2(v0, v1);
            *(uint32_t*)(g_atthi + rowb + nt * 8) = hp;
            *(uint32_t*)(g_attlo + rowb + nt * 8) = pack_resid(hp, v0, v1);
        }
    }
}

// ---------------------------------------------------------------------------
extern "C" void kernel_launch(void* const* d_in, const int* in_sizes, int n_in,
                              void* d_out, int out_size)
{
    const float* x      = (const float*)d_in[0];
    const float* wq     = (const float*)d_in[1];
    const float* wk     = (const float*)d_in[2];
    const float* wv     = (const float*)d_in[3];
    const float* w_proj = (const float*)d_in[4];
    const float* b_proj = (const float*)d_in[5];
    float* out = (float*)d_out;

    cudaFuncSetAttribute(qkv_tc3, cudaFuncAttributeMaxDynamicSharedMemorySize, 2 * QST);
    cudaFuncSetAttribute(gemm_proj, cudaFuncAttributeMaxDynamicSharedMemorySize, 2 * ST_SZ);
    cudaFuncSetAttribute(attn_tc, cudaFuncAttributeMaxDynamicSharedMemorySize, ATT_SMEM);

    prep_x<<<(BT * EMB + 255) / 256, 256>>>(x);
    prep_w<<<(3 * HH * DD * EMB + 255) / 256, 256>>>(wq, wk, wv);
    prep_wp<<<(EMB * EMB + 255) / 256, 256>>>(w_proj);

    qkv_tc3<<<dim3(1152 / 128, BT / 128), 256, 2 * QST>>>();
    attn_tc<<<dim3(TT / 128, BB * HH), 256, ATT_SMEM>>>();
    gemm_proj<<<dim3(EMB / 128, BT / 128), 256, 2 * ST_SZ>>>(b_proj, out);
}

// round 7
// speedup vs baseline: 1.6293x; 1.2131x over previous
#include <cuda_runtime.h>
#include <cuda_bf16.h>
#include <cuda_fp16.h>
#include <cstdint>

#define BB 256
#define TT 256
#define EMB 384
#define HH 6
#define DD 64
#define BT (BB*TT)

// ---------------------------------------------------------------------------
// Scratch (__device__ globals — allocation-free rule).  All fp16 now.
// ---------------------------------------------------------------------------
__device__ __align__(16) __half g_qhi[BB * HH * TT * DD];
__device__ __align__(16) __half g_qlo[BB * HH * TT * DD];
__device__ __align__(16) __half g_khi[BB * HH * TT * DD];   // hi only (B-side)
__device__ __align__(16) __half g_vhi[BB * HH * TT * DD];   // hi only (B-side)
__device__ __align__(16) __half g_xhi[BT * EMB];
__device__ __align__(16) __half g_xlo[BT * EMB];
__device__ __align__(16) __half g_wthi[3 * HH * DD * EMB];  // [n=z*384+h*64+d][e]
__device__ __align__(16) __half g_wphi[EMB * EMB];          // [n][k] hi only
__device__ __align__(16) __half g_atthi[BT * EMB];
__device__ __align__(16) __half g_attlo[BT * EMB];

// ---------------------------------------------------------------------------
// mma.sync / ldmatrix / cp.async helpers
// ---------------------------------------------------------------------------
__device__ __forceinline__ uint32_t smem_u32(const void* p) {
    uint32_t a;
    asm("{ .reg .u64 t; cvta.to.shared.u64 t, %1; cvt.u32.u64 %0, t; }"
        : "=r"(a) : "l"(p));
    return a;
}
__device__ __forceinline__ void ldm4(uint32_t* r, uint32_t addr) {
    asm volatile("ldmatrix.sync.aligned.m8n8.x4.shared.b16 {%0,%1,%2,%3}, [%4];"
        : "=r"(r[0]), "=r"(r[1]), "=r"(r[2]), "=r"(r[3]) : "r"(addr));
}
__device__ __forceinline__ void ldm4t(uint32_t* r, uint32_t addr) {
    asm volatile("ldmatrix.sync.aligned.m8n8.x4.trans.shared.b16 {%0,%1,%2,%3}, [%4];"
        : "=r"(r[0]), "=r"(r[1]), "=r"(r[2]), "=r"(r[3]) : "r"(addr));
}
__device__ __forceinline__ void mma_f16(float* c, const uint32_t* a, const uint32_t* b) {
    asm volatile(
        "mma.sync.aligned.m16n8k16.row.col.f32.f16.f16.f32 "
        "{%0,%1,%2,%3}, {%4,%5,%6,%7}, {%8,%9}, {%0,%1,%2,%3};"
        : "+f"(c[0]), "+f"(c[1]), "+f"(c[2]), "+f"(c[3])
        : "r"(a[0]), "r"(a[1]), "r"(a[2]), "r"(a[3]), "r"(b[0]), "r"(b[1]));
}
__device__ __forceinline__ void cp16(uint32_t dst, const void* src) {
    asm volatile("cp.async.cg.shared.global [%0], [%1], 16;" :: "r"(dst), "l"(src));
}
#define CP_COMMIT() asm volatile("cp.async.commit_group;" ::: "memory")
#define CP_WAIT_ALL() asm volatile("cp.async.wait_group 0;" ::: "memory")

// fp16x2 pack: .x = lo arg, .y = hi arg
__device__ __forceinline__ uint32_t pack_h2(float lo, float hi) {
    __half2 h = __floats2half2_rn(lo, hi);
    return *(uint32_t*)&h;
}
__device__ __forceinline__ uint32_t resid_h2(uint32_t u, float lo, float hi) {
    __half2 h = *(__half2*)&u;
    float2 f = __half22float2(h);
    return pack_h2(lo - f.x, hi - f.y);
}

// 64B-row tile swizzle (4 units of 16B): u ^ ((r>>1)&3)
__device__ __forceinline__ uint32_t swz(uint32_t r, uint32_t u) {
    return (r << 6) + ((u ^ ((r >> 1) & 3u)) << 4);
}
// 128B-row tile swizzle (8 units of 16B): u ^ (r&7)
__device__ __forceinline__ uint32_t swz8(uint32_t r, uint32_t u) {
    return (r << 7) + ((u ^ (r & 7u)) << 4);
}

// ---------------------------------------------------------------------------
// Prep kernels
// ---------------------------------------------------------------------------
__global__ void prep_x(const float* __restrict__ x) {
    int i = blockIdx.x * 256 + threadIdx.x;
    if (i < BT * EMB) {
        float v = x[i];
        __half h = __float2half(v);
        g_xhi[i] = h;
        g_xlo[i] = __float2half(v - __half2float(h));
    }
}
__global__ void prep_w(const float* __restrict__ wq, const float* __restrict__ wk,
                       const float* __restrict__ wv) {
    int i = blockIdx.x * 256 + threadIdx.x;
    if (i >= 3 * HH * DD * EMB) return;
    int e = i % EMB;
    int d = (i / EMB) % DD;
    int h = (i / (EMB * DD)) % HH;
    int z = i / (EMB * DD * HH);
    const float* w = (z == 0) ? wq : (z == 1) ? wk : wv;
    g_wthi[i] = __float2half(w[(h * EMB + e) * DD + d]);
}
__global__ void prep_wp(const float* __restrict__ wp) {
    int i = blockIdx.x * 256 + threadIdx.x;
    if (i >= EMB * EMB) return;
    int k = i % EMB;
    int n = i / EMB;
    g_wphi[i] = __float2half(wp[k * EMB + n]);
}

// ---------------------------------------------------------------------------
// fp16 2-term GEMM (R6-proven skeleton).  C[M,N] = A[M,384] x B[384,N].
// MODE 0: qkv (B = g_wthi, N=1152; epilogue writes q hi/lo, k hi, v hi)
// MODE 1: proj (B = g_wphi, N=384; epilogue adds bias, writes fp32 out)
// ---------------------------------------------------------------------------
#define QST 24576
#define QOFF_AH 0
#define QOFF_AL 8192
#define QOFF_BH 16384

template<int MODE>
__global__ __launch_bounds__(256, 2) void gemm_f16(const float* __restrict__ bias,
                                                   float* __restrict__ outp)
{
    extern __shared__ char sm[];
    const uint32_t sb = smem_u32(sm);

    const char* AhiB = (const char*)(MODE == 0 ? g_xhi : g_atthi);
    const char* AloB = (const char*)(MODE == 0 ? g_xlo : g_attlo);
    const char* BhiB = (const char*)(MODE == 0 ? g_wthi : g_wphi);

    const int tid  = threadIdx.x;
    const int wid  = tid >> 5;
    const int lane = tid & 31;
    const int m0   = blockIdx.y * 128;
    const int n0   = blockIdx.x * 128;

    const int lr = tid >> 2;
    const int lu = tid & 3;

    const int wm   = (wid >> 1) * 32;
    const int wn   = (wid & 1) * 64;
    const int a_r  = wm + (lane & 15);
    const int a_u0 = (lane >> 4);
    const int b_r  = wn + ((lane >> 4) & 1) * 8 + (lane & 7);
    const int b_u0 = (lane >> 3) & 1;

    float c[2][8][4];
    #pragma unroll
    for (int mt = 0; mt < 2; mt++)
        #pragma unroll
        for (int nt = 0; nt < 8; nt++)
            #pragma unroll
            for (int q = 0; q < 4; q++) c[mt][nt][q] = 0.0f;

    {
        #pragma unroll
        for (int j = 0; j < 2; j++) {
            int r = lr + j * 64;
            size_t ga = (size_t)(m0 + r) * 768 + lu * 16;
            size_t gb = (size_t)(n0 + r) * 768 + lu * 16;
            *(uint4*)(sm + QOFF_AH + swz(r, lu)) = *(const uint4*)(AhiB + ga);
            *(uint4*)(sm + QOFF_AL + swz(r, lu)) = *(const uint4*)(AloB + ga);
            *(uint4*)(sm + QOFF_BH + swz(r, lu)) = *(const uint4*)(BhiB + gb);
        }
    }
    __syncthreads();

    int stage = 0;
    for (int kc = 0; kc < 12; kc++) {
        uint4 v[6];
        if (kc < 11) {
            const int ko = (kc + 1) * 64;
            #pragma unroll
            for (int j = 0; j < 2; j++) {
                int r = lr + j * 64;
                size_t ga = (size_t)(m0 + r) * 768 + ko + lu * 16;
                size_t gb = (size_t)(n0 + r) * 768 + ko + lu * 16;
                v[j * 3 + 0] = *(const uint4*)(AhiB + ga);
                v[j * 3 + 1] = *(const uint4*)(AloB + ga);
                v[j * 3 + 2] = *(const uint4*)(BhiB + gb);
            }
        }

        const uint32_t base = sb + stage * QST;
        #pragma unroll
        for (int ks = 0; ks < 2; ks++) {
            uint32_t ahi[2][4], alo[2][4], bhi[8][2];
            #pragma unroll
            for (int mt = 0; mt < 2; mt++) {
                uint32_t r = a_r + mt * 16;
                uint32_t u = ks * 2 + a_u0;
                ldm4(ahi[mt], base + QOFF_AH + swz(r, u));
                ldm4(alo[mt], base + QOFF_AL + swz(r, u));
            }
            #pragma unroll
            for (int p = 0; p < 4; p++) {
                uint32_t r = b_r + p * 16;
                uint32_t u = ks * 2 + b_u0;
                uint32_t t4[4];
                ldm4(t4, base + QOFF_BH + swz(r, u));
                bhi[2 * p][0] = t4[0]; bhi[2 * p][1] = t4[1];
                bhi[2 * p + 1][0] = t4[2]; bhi[2 * p + 1][1] = t4[3];
            }
            #pragma unroll
            for (int mt = 0; mt < 2; mt++)
                #pragma unroll
                for (int nt = 0; nt < 8; nt++) {
                    mma_f16(c[mt][nt], ahi[mt], bhi[nt]);
                    mma_f16(c[mt][nt], alo[mt], bhi[nt]);
                }
        }

        if (kc < 11) {
            char* dst = sm + (stage ^ 1) * QST;
            #pragma unroll
            for (int j = 0; j < 2; j++) {
                int r = lr + j * 64;
                *(uint4*)(dst + QOFF_AH + swz(r, lu)) = v[j * 3 + 0];
                *(uint4*)(dst + QOFF_AL + swz(r, lu)) = v[j * 3 + 1];
                *(uint4*)(dst + QOFF_BH + swz(r, lu)) = v[j * 3 + 2];
            }
        }
        __syncthreads();
        stage ^= 1;
    }

    const int row0 = lane >> 2;
    const int col0 = (lane & 3) * 2;

    if (MODE == 0) {
        const int z = n0 / 384;
        const int nloc = n0 % 384;
        const float scl = (z == 0) ? 0.125f : 1.0f;
        __half* dhi = (z == 0) ? g_qhi : (z == 1) ? g_khi : g_vhi;
        #pragma unroll
        for (int mt = 0; mt < 2; mt++)
            #pragma unroll
            for (int half = 0; half < 2; half++) {
                int m = m0 + wm + mt * 16 + row0 + half * 8;
                int b = m >> 8, t = m & 255;
                #pragma unroll
                for (int nt = 0; nt < 8; nt++) {
                    int n = nloc + wn + nt * 8 + col0;
                    int h = n >> 6, d = n & 63;
                    size_t idx = (((size_t)b * HH + h) * TT + t) * DD + d;
                    float v0 = c[mt][nt][half * 2] * scl;
                    float v1 = c[mt][nt][half * 2 + 1] * scl;
                    uint32_t hp = pack_h2(v0, v1);
                    *(uint32_t*)(dhi + idx) = hp;
                    if (z == 0)
                        *(uint32_t*)(g_qlo + idx) = resid_h2(hp, v0, v1);
                }
            }
    } else {
        #pragma unroll
        for (int mt = 0; mt < 2; mt++)
            #pragma unroll
            for (int half = 0; half < 2; half++) {
                int m = m0 + wm + mt * 16 + row0 + half * 8;
                #pragma unroll
                for (int nt = 0; nt < 8; nt++) {
                    int n = n0 + wn + nt * 8 + col0;
                    float2 val = make_float2(c[mt][nt][half * 2] + bias[n],
                                             c[mt][nt][half * 2 + 1] + bias[n + 1]);
                    *(float2*)(outp + (size_t)m * EMB + n) = val;
                }
            }
    }
}

// ---------------------------------------------------------------------------
// fp16 flash attention, 2-term (S = Qh.Kh + Ql.Kh ; PV = Ph.Vh + Pl.Vh).
// K/V tiles (hi only) cp.async double-buffered. smem = Q 32KB + 2x32KB = 96KB.
// ---------------------------------------------------------------------------
#define AQHI 0
#define AQLO 16384
#define AKV0 32768           // stage s: K at AKV0 + s*32768, V at +16384
#define ATT_SMEM 98304

__global__ __launch_bounds__(256) void attn_tc()
{
    extern __shared__ char sm[];
    const uint32_t sb = smem_u32(sm);
    const int qt  = blockIdx.x;
    const int bh  = blockIdx.y;
    const int tid = threadIdx.x;
    const int wid = tid >> 5;
    const int lane = tid & 31;

    const __half* qhi = g_qhi + ((size_t)bh * TT + qt * 128) * DD;
    const __half* qlo = g_qlo + ((size_t)bh * TT + qt * 128) * DD;
    const __half* khi = g_khi + (size_t)bh * TT * DD;
    const __half* vhi = g_vhi + (size_t)bh * TT * DD;

    // Q hi/lo via cp.async (overlaps with first K/V tile load below)
    #pragma unroll
    for (int j = 0; j < 8; j++) {
        int idx = tid + 256 * j;
        int arr = idx >> 10;
        int r = (idx >> 3) & 127;
        int u = idx & 7;
        const __half* src = arr ? qlo : qhi;
        cp16(sb + (arr ? AQLO : AQHI) + swz8(r, u), src + (size_t)r * DD + u * 8);
    }
    // K/V tile 0 into stage 0
    #pragma unroll
    for (int j = 0; j < 8; j++) {
        int idx = tid + 256 * j;
        int arr = idx >> 10;                  // 0 = K, 1 = V
        int r = (idx >> 3) & 127;
        int u = idx & 7;
        const __half* src = arr ? vhi : khi;
        cp16(sb + AKV0 + arr * 16384 + swz8(r, u), src + (size_t)r * DD + u * 8);
    }
    CP_COMMIT();
    CP_WAIT_ALL();
    __syncthreads();

    // Q fragments
    uint32_t qfh[4][4], qfl[4][4];
    {
        int ar = wid * 16 + (lane & 15);
        #pragma unroll
        for (int kc = 0; kc < 4; kc++) {
            int u = kc * 2 + (lane >> 4);
            ldm4(qfh[kc], sb + AQHI + swz8(ar, u));
            ldm4(qfl[kc], sb + AQLO + swz8(ar, u));
        }
    }

    float o[8][4];
    #pragma unroll
    for (int nt = 0; nt < 8; nt++)
        #pragma unroll
        for (int q = 0; q < 4; q++) o[nt][q] = 0.0f;
    float mx[2] = {-1e30f, -1e30f};
    float lsum[2] = {0.0f, 0.0f};

    for (int kt = 0; kt <= qt; kt++) {
        const uint32_t kvb = sb + AKV0 + (kt & 1) * 32768;

        // prefetch next K/V tile into other stage (overlapped with compute)
        if (kt < qt) {
            #pragma unroll
            for (int j = 0; j < 8; j++) {
                int idx = tid + 256 * j;
                int arr = idx >> 10;
                int r = (idx >> 3) & 127;
                int u = idx & 7;
                const __half* src = arr ? vhi : khi;
                cp16(sb + AKV0 + ((kt + 1) & 1) * 32768 + arr * 16384 + swz8(r, u),
                     src + ((size_t)(kt + 1) * 128 + r) * DD + u * 8);
            }
            CP_COMMIT();
        }

        // S = Q K^T (2-term)
        float s[16][4];
        #pragma unroll
        for (int nt = 0; nt < 16; nt++)
            #pragma unroll
            for (int q = 0; q < 4; q++) s[nt][q] = 0.0f;

        #pragma unroll
        for (int np = 0; np < 8; np++) {
            int br = np * 16 + ((lane >> 4) & 1) * 8 + (lane & 7);
            #pragma unroll
            for (int kc = 0; kc < 4; kc++) {
                int u = kc * 2 + ((lane >> 3) & 1);
                uint32_t th[4];
                ldm4(th, kvb + swz8(br, u));
                uint32_t b0h[2] = {th[0], th[1]}, b1h[2] = {th[2], th[3]};
                mma_f16(s[2 * np], qfh[kc], b0h);
                mma_f16(s[2 * np], qfl[kc], b0h);
                mma_f16(s[2 * np + 1], qfh[kc], b1h);
                mma_f16(s[2 * np + 1], qfl[kc], b1h);
            }
        }

        if (kt == qt) {
            #pragma unroll
            for (int nt = 0; nt < 16; nt++)
                #pragma unroll
                for (int q = 0; q < 4; q++) {
                    int col = nt * 8 + (lane & 3) * 2 + (q & 1);
                    int row = wid * 16 + (lane >> 2) + (q >> 1) * 8;
                    if (col > row) s[nt][q] = -1e30f;
                }
        }

        float al[2];
        #pragma unroll
        for (int hf = 0; hf < 2; hf++) {
            float rm = -1e30f;
            #pragma unroll
            for (int nt = 0; nt < 16; nt++)
                rm = fmaxf(rm, fmaxf(s[nt][hf * 2], s[nt][hf * 2 + 1]));
            rm = fmaxf(rm, __shfl_xor_sync(0xffffffffu, rm, 1));
            rm = fmaxf(rm, __shfl_xor_sync(0xffffffffu, rm, 2));
            float mn = fmaxf(mx[hf], rm);
            al[hf] = __expf(mx[hf] - mn);
            mx[hf] = mn;
            float ps = 0.0f;
            #pragma unroll
            for (int nt = 0; nt < 16; nt++) {
                s[nt][hf * 2]     = __expf(s[nt][hf * 2] - mn);
                s[nt][hf * 2 + 1] = __expf(s[nt][hf * 2 + 1] - mn);
                ps += s[nt][hf * 2] + s[nt][hf * 2 + 1];
            }
            ps += __shfl_xor_sync(0xffffffffu, ps, 1);
            ps += __shfl_xor_sync(0xffffffffu, ps, 2);
            lsum[hf] = lsum[hf] * al[hf] + ps;
        }
        #pragma unroll
        for (int nt = 0; nt < 8; nt++) {
            o[nt][0] *= al[0]; o[nt][1] *= al[0];
            o[nt][2] *= al[1]; o[nt][3] *= al[1];
        }

        // O += P V (2-term; V hi only)
        #pragma unroll
        for (int kc = 0; kc < 8; kc++) {
            uint32_t ah[4], al4[4];
            ah[0] = pack_h2(s[2 * kc][0], s[2 * kc][1]);
            ah[1] = pack_h2(s[2 * kc][2], s[2 * kc][3]);
            ah[2] = pack_h2(s[2 * kc + 1][0], s[2 * kc + 1][1]);
            ah[3] = pack_h2(s[2 * kc + 1][2], s[2 * kc + 1][3]);
            al4[0] = resid_h2(ah[0], s[2 * kc][0], s[2 * kc][1]);
            al4[1] = resid_h2(ah[1], s[2 * kc][2], s[2 * kc][3]);
            al4[2] = resid_h2(ah[2], s[2 * kc + 1][0], s[2 * kc + 1][1]);
            al4[3] = resid_h2(ah[3], s[2 * kc + 1][2], s[2 * kc + 1][3]);

            int vr = kc * 16 + ((lane >> 3) & 1) * 8 + (lane & 7);
            #pragma unroll
            for (int ntp = 0; ntp < 4; ntp++) {
                int u = ntp * 2 + (lane >> 4);
                uint32_t th[4];
                ldm4t(th, kvb + 16384 + swz8(vr, u));
                uint32_t b0h[2] = {th[0], th[1]}, b1h[2] = {th[2], th[3]};
                mma_f16(o[2 * ntp], ah, b0h);
                mma_f16(o[2 * ntp], al4, b0h);
                mma_f16(o[2 * ntp + 1], ah, b1h);
                mma_f16(o[2 * ntp + 1], al4, b1h);
            }
        }

        // next tile ready + all warps done with current buffers
        if (kt < qt) {
            CP_WAIT_ALL();
            __syncthreads();
        }
    }

    // epilogue: normalize, write fp16 hi/lo att rows [BT][EMB]
    const int b = bh / HH, h = bh % HH;
    #pragma unroll
    for (int hf = 0; hf < 2; hf++) {
        float inv = 1.0f / lsum[hf];
        int t = qt * 128 + wid * 16 + (lane >> 2) + hf * 8;
        size_t rowb = ((size_t)b * TT + t) * EMB + h * 64 + (lane & 3) * 2;
        #pragma unroll
        for (int nt = 0; nt < 8; nt++) {
            float v0 = o[nt][hf * 2] * inv;
            float v1 = o[nt][hf * 2 + 1] * inv;
            uint32_t hp = pack_h2(v0, v1);
            *(uint32_t*)(g_atthi + rowb + nt * 8) = hp;
            *(uint32_t*)(g_attlo + rowb + nt * 8) = resid_h2(hp, v0, v1);
        }
    }
}

// ---------------------------------------------------------------------------
extern "C" void kernel_launch(void* const* d_in, const int* in_sizes, int n_in,
                              void* d_out, int out_size)
{
    const float* x      = (const float*)d_in[0];
    const float* wq     = (const float*)d_in[1];
    const float* wk     = (const float*)d_in[2];
    const float* wv     = (const float*)d_in[3];
    const float* w_proj = (const float*)d_in[4];
    const float* b_proj = (const float*)d_in[5];
    float* out = (float*)d_out;

    cudaFuncSetAttribute(gemm_f16<0>, cudaFuncAttributeMaxDynamicSharedMemorySize, 2 * QST);
    cudaFuncSetAttribute(gemm_f16<1>, cudaFuncAttributeMaxDynamicSharedMemorySize, 2 * QST);
    cudaFuncSetAttribute(attn_tc, cudaFuncAttributeMaxDynamicSharedMemorySize, ATT_SMEM);

    prep_x<<<(BT * EMB + 255) / 256, 256>>>(x);
    prep_w<<<(3 * HH * DD * EMB + 255) / 256, 256>>>(wq, wk, wv);
    prep_wp<<<(EMB * EMB + 255) / 256, 256>>>(w_proj);

    gemm_f16<0><<<dim3(1152 / 128, BT / 128), 256, 2 * QST>>>(nullptr, nullptr);
    attn_tc<<<dim3(TT / 128, BB * HH), 256, ATT_SMEM>>>();
    gemm_f16<1><<<dim3(EMB / 128, BT / 128), 256, 2 * QST>>>(b_proj, out);
}